// round 14
// baseline (speedup 1.0000x reference)
#include <cuda_runtime.h>
#include <math.h>
#include <stdint.h>

#define NN 128
#define MM (NN*NN)
#define KTOP 2
#define TMAXS 512
#define STEPF 0.01f
#define EPSV 1e-5f
#define BSZ 512

// ---------------- device scratch (static, no allocations) ----------------
__device__ float g_S [5*MM];   // skew(Z)
__device__ float g_S2[5*MM];   // S^2
__device__ float g_S3[5*MM];   // S^3
__device__ float g_P0[5*MM];   // Horner ping (FINAL expm lands here)
__device__ float g_P1[5*MM];   // Horner pong
__device__ float g_MA[MM];     // I + STEP*A    (row-major)
__device__ float g_MB[MM];     // STEP*B        (row-major)
__device__ float g_MC[MM];     // C             (row-major)

__device__ __forceinline__ float* selbuf(int s) {
    switch (s) { case 0: return g_S; case 1: return g_S2; case 2: return g_S3;
                 case 3: return g_P0; default: return g_P1; }
}

// ---------------- f32x2 helpers ----------------
typedef unsigned long long ull;
__device__ __forceinline__ ull rep2(float v) {
    ull r; asm("mov.b64 %0, {%1, %1};" : "=l"(r) : "f"(v)); return r;
}
__device__ __forceinline__ ull pk2(float lo, float hi) {
    ull r; asm("mov.b64 %0, {%1, %2};" : "=l"(r) : "f"(lo), "f"(hi)); return r;
}
__device__ __forceinline__ void fma2(ull& a, ull b, ull c) {
    asm("fma.rn.f32x2 %0, %1, %2, %0;" : "+l"(a) : "l"(b), "l"(c));
}
__device__ __forceinline__ void unpk(float& lo, float& hi, ull v) {
    asm("mov.b64 {%0, %1}, %2;" : "=f"(lo), "=f"(hi) : "l"(v));
}
__device__ __forceinline__ float tanha(float x) {
    float r; asm("tanh.approx.f32 %0, %1;" : "=f"(r) : "f"(x)); return r;
}

// ---------------- prep: S = skew(Z) ----------------
__global__ void prep_kernel(const float* UA, const float* UB, const float* VB,
                            const float* UC, const float* VC) {
    int m = blockIdx.x;
    const float* Z;
    switch (m) { case 0: Z = UA; break; case 1: Z = UB; break; case 2: Z = VB; break;
                 case 3: Z = UC; break; default: Z = VC; break; }
    for (int idx = blockIdx.y * blockDim.x + threadIdx.x; idx < MM;
         idx += gridDim.y * blockDim.x) {
        int i = idx >> 7, j = idx & 127;
        float v = (i < j) ? Z[idx] : ((i > j) ? -Z[j*NN + i] : 0.0f);
        g_S[m*MM + idx] = v;
    }
}

// ---------------- 32x32-tiled batched stage ------------------------------
// O = L@R + eI*I + eS*S + eS2*S2
// dual!=0: O = L@R, and P0 = dI*I + dS*S + dS2*S2 + dA*(L@R)
__global__ __launch_bounds__(256) void mm32_kernel(int lsel, int rsel, int osel,
                                                   float eI, float eS, float eS2,
                                                   int dual, float dI, float dS,
                                                   float dS2, float dA) {
    __shared__ float LsT[128][36];   // [k][r]
    __shared__ float Rs [128][34];   // [k][j]
    int m = blockIdx.y;
    const float* L = selbuf(lsel) + m*MM;
    const float* R = selbuf(rsel) + m*MM;
    float*       O = selbuf(osel) + m*MM;
    const float* Sm  = g_S  + m*MM;
    const float* S2m = g_S2 + m*MM;
    float*       P0m = g_P0 + m*MM;
    int r0 = (blockIdx.x >> 2) * 32;
    int j0 = (blockIdx.x & 3) * 32;
    int tid = threadIdx.x;

    for (int idx = tid; idx < 32*128; idx += 256) {
        int r = idx >> 7, k = idx & 127;
        LsT[k][r] = L[(r0 + r)*NN + k];
    }
    for (int idx = tid; idx < 128*32; idx += 256) {
        int k = idx >> 5, j = idx & 31;
        Rs[k][j] = R[k*NN + j0 + j];
    }
    __syncthreads();

    int rp = tid >> 4, cp = tid & 15;
    int r = 2*rp, c = 2*cp;
    float a00=0, a01=0, a10=0, a11=0;
    #pragma unroll 8
    for (int k = 0; k < 128; k++) {
        float2 lv = *(const float2*)&LsT[k][r];
        float2 rv = *(const float2*)&Rs[k][c];
        a00 += lv.x*rv.x; a01 += lv.x*rv.y;
        a10 += lv.y*rv.x; a11 += lv.y*rv.y;
    }
    float acc[2][2] = {{a00, a01}, {a10, a11}};
    #pragma unroll
    for (int a = 0; a < 2; a++) {
        int i = r0 + r + a;
        int base = i*NN + j0 + c;
        #pragma unroll
        for (int b = 0; b < 2; b++) {
            int j = j0 + c + b;
            float v = acc[a][b];
            float id = (i == j) ? 1.0f : 0.0f;
            if (dual) {
                O[base + b]   = v;
                P0m[base + b] = dI*id + dS*Sm[base + b] + dS2*S2m[base + b] + dA*v;
            } else {
                O[base + b]   = v + eI*id + eS*Sm[base + b] + eS2*S2m[base + b];
            }
        }
    }
}

// ---------------- build row-major MA/MB/MC: O = epi(L @ diag(d) @ R^T) ----
// sa diagonal computed in-kernel by mode-0 blocks (parallel, no scal kernel)
__global__ __launch_bounds__(256) void build32_kernel(const float* SB, const float* SC,
                                                      const float* YA,
                                                      const float* GA_ks1,
                                                      const float* GA_k,
                                                      const float* GA_kp1) {
    __shared__ float LsT[128][36];   // [k][r] = L[r][k]*d[k]
    __shared__ float RjT[128][36];   // [k][j] = R[j][k]
    __shared__ float ds[128];
    __shared__ float rsa[3];
    int mode = blockIdx.y;
    const float* L; const float* R;
    if (mode == 0)      { L = g_P0 + 0*MM; R = g_P0 + 0*MM; }   // A: UA_w, UA_w
    else if (mode == 1) { L = g_P0 + 1*MM; R = g_P0 + 2*MM; }   // B: UB_w, VB_w
    else                { L = g_P0 + 3*MM; R = g_P0 + 4*MM; }   // C: UC_w, VC_w
    int r0 = (blockIdx.x >> 2) * 32;
    int j0 = (blockIdx.x & 3) * 32;
    int tid = threadIdx.x;

    if (mode == 0 && tid < 32) {
        float b1=-1.0f, b2=-1.0f, c1=-1.0f, c2=-1.0f;
        #pragma unroll
        for (int u = 0; u < 4; u++) {
            int i = tid + 32*u;
            float v = fabsf(SB[i*NN + i]);
            if (v > b1) { b2 = b1; b1 = v; } else if (v > b2) b2 = v;
            float w = fabsf(SC[i*NN + i]);
            if (w > c1) { c2 = c1; c1 = w; } else if (w > c2) c2 = w;
        }
        #pragma unroll
        for (int off = 16; off; off >>= 1) {
            float ob1 = __shfl_down_sync(0xffffffffu, b1, off);
            float ob2 = __shfl_down_sync(0xffffffffu, b2, off);
            if (ob1 > b1) { b2 = fmaxf(b1, ob2); b1 = ob1; } else b2 = fmaxf(b2, ob1);
            float oc1 = __shfl_down_sync(0xffffffffu, c1, off);
            float oc2 = __shfl_down_sync(0xffffffffu, c2, off);
            if (oc1 > c1) { c2 = fmaxf(c1, oc2); c1 = oc1; } else c2 = fmaxf(c2, oc1);
        }
        if (tid == 0) {
            float sum = b1*b1*c1*c1 + b2*b2*c2*c2;
            float alpha = sqrtf(4.0f * (float)KTOP * sum);   // G = 1
            float sa0 = GA_ks1[0];
            float sa1 = -(alpha + sa0) - (fabsf(GA_k[0]) + EPSV);
            float mn = fminf(fminf(sa0, sa1), 0.0f);
            rsa[0] = sa0; rsa[1] = sa1; rsa[2] = mn;
        }
    }
    __syncthreads();
    if (tid < NN) {
        if (mode == 0)
            ds[tid] = (tid == 0) ? rsa[0]
                    : (tid == 1) ? rsa[1]
                    : rsa[2] - fabsf(GA_kp1[(tid - 2) * 127]);   // stride nsk+1
        else
            ds[tid] = (mode == 1) ? fabsf(SB[tid*NN + tid]) : fabsf(SC[tid*NN + tid]);
    }
    __syncthreads();
    for (int idx = tid; idx < 32*128; idx += 256) {
        int r = idx >> 7, k = idx & 127;
        LsT[k][r] = L[(r0 + r)*NN + k] * ds[k];
    }
    for (int idx = tid; idx < 32*128; idx += 256) {
        int j = idx >> 7, k = idx & 127;
        RjT[k][j] = R[(j0 + j)*NN + k];
    }
    __syncthreads();

    int rp = tid >> 4, cp = tid & 15;
    int r = 2*rp, c = 2*cp;
    float a00=0, a01=0, a10=0, a11=0;
    #pragma unroll 8
    for (int k = 0; k < 128; k++) {
        float2 lv = *(const float2*)&LsT[k][r];
        float2 rv = *(const float2*)&RjT[k][c];
        a00 += lv.x*rv.x; a01 += lv.x*rv.y;
        a10 += lv.y*rv.x; a11 += lv.y*rv.y;
    }
    float acc[2][2] = {{a00, a01}, {a10, a11}};
    #pragma unroll
    for (int a = 0; a < 2; a++) {
        int i = r0 + r + a;
        #pragma unroll
        for (int b = 0; b < 2; b++) {
            int j = j0 + c + b;
            float v = acc[a][b];
            if (mode == 0) {   // MA = I + STEP*(0.5*UA SA UA^T + 0.5*skew(YA))
                float sk = (i < j) ? YA[i*NN + j] : ((i > j) ? -YA[j*NN + i] : 0.0f);
                g_MA[i*NN + j] = ((i == j) ? 1.0f : 0.0f)
                               + 0.5f*STEPF*v + 0.5f*STEPF*sk;
            } else if (mode == 1) {
                g_MB[i*NN + j] = STEPF * v;
            } else {
                g_MC[i*NN + j] = v;
            }
        }
    }
}

// ---------------- recurrence: 128 blocks, 256 threads, 4 cols/block ------
// thread (r,c): row r = tid&127, col-pair c = tid>>7 (cols 2c, 2c+1).
// Full rows of A/B/C register-resident (192 regs); X/T broadcast via SMEM.
// No cross-thread reduction, no shuffles.
__global__ __launch_bounds__(256, 1) void recur_kernel(
        const float* __restrict__ X0,
        const float* __restrict__ bx,
        const float* __restrict__ by,
        float* __restrict__ out) {
    __shared__ float sX[4*NN];
    __shared__ float sT[4*NN];
    const int tid = threadIdx.x;
    const int r = tid & 127;
    const int c = tid >> 7;
    const int b0 = blockIdx.x << 2;
    const int c0 = 2*c, c1 = 2*c + 1;

    // full rows, k-pair packed: 64 ull per matrix
    ull rA2[64], rB2[64], rC2[64];
    {
        const ull* Ap = (const ull*)(g_MA + r*NN);
        const ull* Bp = (const ull*)(g_MB + r*NN);
        const ull* Cp = (const ull*)(g_MC + r*NN);
        #pragma unroll
        for (int j = 0; j < 64; j++) { rA2[j] = Ap[j]; rB2[j] = Bp[j]; rC2[j] = Cp[j]; }
    }

    float v0 = X0[(b0 + c0)*NN + r];
    float v1 = X0[(b0 + c1)*NN + r];
    sX[c0*NN + r] = v0;
    sX[c1*NN + r] = v1;

    float* p0 = out + ((size_t)(b0 + c0)*TMAXS)*NN + r;
    float* p1 = out + ((size_t)(b0 + c1)*TMAXS)*NN + r;
    *p0 = v0; *p1 = v1; p0 += NN; p1 += NN;

    const float byr = by[r];
    const float bxr = STEPF * bx[r];
    __syncthreads();

    const ulonglong2* xa = (const ulonglong2*)(sX + c0*NN);
    const ulonglong2* xb = (const ulonglong2*)(sX + c1*NN);
    const ulonglong2* ta = (const ulonglong2*)(sT + c0*NN);
    const ulonglong2* tb = (const ulonglong2*)(sT + c1*NN);

    for (int t = 1; t < TMAXS; t++) {
        ull aA0 = pk2(bxr, 0.0f), aA1 = pk2(bxr, 0.0f);
        ull aY0 = pk2(byr, 0.0f), aY1 = pk2(byr, 0.0f);
        #pragma unroll
        for (int kk2 = 0; kk2 < 32; kk2++) {
            ulonglong2 x0 = xa[kk2];
            ulonglong2 x1 = xb[kk2];
            ull alo = rA2[2*kk2], ahi = rA2[2*kk2+1];
            ull clo = rC2[2*kk2], chi = rC2[2*kk2+1];
            fma2(aA0, alo, x0.x); fma2(aA0, ahi, x0.y);
            fma2(aA1, alo, x1.x); fma2(aA1, ahi, x1.y);
            fma2(aY0, clo, x0.x); fma2(aY0, chi, x0.y);
            fma2(aY1, clo, x1.x); fma2(aY1, chi, x1.y);
        }
        float lo, hi, y0, y1;
        unpk(lo, hi, aY0); y0 = lo + hi;
        unpk(lo, hi, aY1); y1 = lo + hi;
        sT[c0*NN + r] = tanha(y0);
        sT[c1*NN + r] = tanha(y1);
        __syncthreads();

        #pragma unroll
        for (int kk2 = 0; kk2 < 32; kk2++) {
            ulonglong2 t0 = ta[kk2];
            ulonglong2 t1 = tb[kk2];
            ull blo = rB2[2*kk2], bhi = rB2[2*kk2+1];
            fma2(aA0, blo, t0.x); fma2(aA0, bhi, t0.y);
            fma2(aA1, blo, t1.x); fma2(aA1, bhi, t1.y);
        }
        float n0, n1;
        unpk(lo, hi, aA0); n0 = lo + hi;
        unpk(lo, hi, aA1); n1 = lo + hi;
        sX[c0*NN + r] = n0;
        sX[c1*NN + r] = n1;
        *p0 = n0; *p1 = n1; p0 += NN; p1 += NN;
        __syncthreads();
    }
}

// ---------------- host launcher ----------------
extern "C" void kernel_launch(void* const* d_in, const int* in_sizes, int n_in,
                              void* d_out, int out_size) {
    const float* X0      = (const float*)d_in[0];
    const float* GA_ks1  = (const float*)d_in[1];
    const float* GA_k    = (const float*)d_in[2];
    const float* GA_kp1  = (const float*)d_in[3];
    const float* YA      = (const float*)d_in[4];
    const float* UA      = (const float*)d_in[5];
    const float* UB      = (const float*)d_in[6];
    const float* VB      = (const float*)d_in[7];
    const float* SB      = (const float*)d_in[8];
    const float* UC      = (const float*)d_in[9];
    const float* VC      = (const float*)d_in[10];
    const float* SC      = (const float*)d_in[11];
    const float* bx      = (const float*)d_in[12];
    const float* by      = (const float*)d_in[13];
    float* out = (float*)d_out;

    // Taylor 1/m!
    const float c3 = 1.6666667e-1f, c4 = 4.1666667e-2f, c5 = 8.3333333e-3f;
    const float c6 = 1.3888889e-3f, c7 = 1.9841270e-4f, c8 = 2.4801587e-5f;
    const float c9 = 2.7557319e-6f;

    // 1) S = skew(Z)
    prep_kernel<<<dim3(5, 16), 256>>>(UA, UB, VB, UC, VC);

    // 2) expm via degree-9 Taylor, Paterson-Stockmeyer (Z = S^3), 4 GEMMs:
    //    S2 = S*S
    mm32_kernel<<<dim3(16, 5), 256>>>(0, 0, 1, 0,0,0, 0, 0,0,0,0);
    //    S3 = S2*S; dual epilogue: P0 = Q1 = c6*I + c7*S + c8*S2 + c9*S3
    mm32_kernel<<<dim3(16, 5), 256>>>(1, 0, 2, 0,0,0, 1, c6, c7, c8, c9);
    //    P1 = Q1*Z + B1
    mm32_kernel<<<dim3(16, 5), 256>>>(3, 2, 4, c3, c4, c5, 0, 0,0,0,0);
    //    P0 = P1*Z + B0   (FINAL expm in g_P0)
    mm32_kernel<<<dim3(16, 5), 256>>>(4, 2, 3, 1.0f, 1.0f, 0.5f, 0, 0,0,0,0);

    // 3) build row-major MA/MB/MC (sa diagonal computed in-kernel)
    build32_kernel<<<dim3(16, 3), 256>>>(SB, SC, YA, GA_ks1, GA_k, GA_kp1);

    // 4) sequential recurrence, batch split across 128 independent blocks
    recur_kernel<<<128, 256>>>(X0, bx, by, out);

    (void)in_sizes; (void)n_in; (void)out_size;
}

// round 15
// speedup vs baseline: 3.4749x; 3.4749x over previous
#include <cuda_runtime.h>
#include <math.h>
#include <stdint.h>

#define NN 128
#define MM (NN*NN)
#define KTOP 2
#define TMAXS 512
#define STEPF 0.01f
#define EPSV 1e-5f
#define BSZ 512

// ---------------- device scratch (static, no allocations) ----------------
__device__ float g_S [5*MM];   // skew(Z)
__device__ float g_S2[5*MM];   // S^2
__device__ float g_S3[5*MM];   // S^3
__device__ float g_P0[5*MM];   // Horner ping (FINAL expm lands here)
__device__ float g_P1[5*MM];   // Horner pong
__device__ float g_MA[MM];     // I + STEP*A    (row-major)
__device__ float g_MB[MM];     // STEP*B        (row-major)
__device__ float g_MC[MM];     // C             (row-major)

__device__ __forceinline__ float* selbuf(int s) {
    switch (s) { case 0: return g_S; case 1: return g_S2; case 2: return g_S3;
                 case 3: return g_P0; default: return g_P1; }
}

// ---------------- f32x2 helpers ----------------
typedef unsigned long long ull;
__device__ __forceinline__ ull rep2(float v) {
    ull r; asm("mov.b64 %0, {%1, %1};" : "=l"(r) : "f"(v)); return r;
}
__device__ __forceinline__ ull pk2(float lo, float hi) {
    ull r; asm("mov.b64 %0, {%1, %2};" : "=l"(r) : "f"(lo), "f"(hi)); return r;
}
__device__ __forceinline__ void fma2(ull& a, ull b, ull c) {
    asm("fma.rn.f32x2 %0, %1, %2, %0;" : "+l"(a) : "l"(b), "l"(c));
}
__device__ __forceinline__ void add2(ull& a, ull b) {
    asm("add.rn.f32x2 %0, %0, %1;" : "+l"(a) : "l"(b));
}
__device__ __forceinline__ void unpk(float& lo, float& hi, ull v) {
    asm("mov.b64 {%0, %1}, %2;" : "=f"(lo), "=f"(hi) : "l"(v));
}
__device__ __forceinline__ float tanha(float x) {
    float r; asm("tanh.approx.f32 %0, %1;" : "=f"(r) : "f"(x)); return r;
}

// ---------------- prep: S = skew(Z) ----------------
__global__ void prep_kernel(const float* UA, const float* UB, const float* VB,
                            const float* UC, const float* VC) {
    int m = blockIdx.x;
    const float* Z;
    switch (m) { case 0: Z = UA; break; case 1: Z = UB; break; case 2: Z = VB; break;
                 case 3: Z = UC; break; default: Z = VC; break; }
    for (int idx = blockIdx.y * blockDim.x + threadIdx.x; idx < MM;
         idx += gridDim.y * blockDim.x) {
        int i = idx >> 7, j = idx & 127;
        float v = (i < j) ? Z[idx] : ((i > j) ? -Z[j*NN + i] : 0.0f);
        g_S[m*MM + idx] = v;
    }
}

// ---------------- 32x32-tiled batched stage (512 thr, 1x2 per thread) ----
// O = L@R + eI*I + eS*S + eS2*S2
// dual!=0: O = L@R, and P0 = dI*I + dS*S + dS2*S2 + dA*(L@R)
__global__ __launch_bounds__(512) void mm32_kernel(int lsel, int rsel, int osel,
                                                   float eI, float eS, float eS2,
                                                   int dual, float dI, float dS,
                                                   float dS2, float dA) {
    __shared__ float LsT[128][36];   // [k][r]
    __shared__ float Rs [128][34];   // [k][j]
    int m = blockIdx.y;
    const float* L = selbuf(lsel) + m*MM;
    const float* R = selbuf(rsel) + m*MM;
    float*       O = selbuf(osel) + m*MM;
    const float* Sm  = g_S  + m*MM;
    const float* S2m = g_S2 + m*MM;
    float*       P0m = g_P0 + m*MM;
    int r0 = (blockIdx.x >> 2) * 32;
    int j0 = (blockIdx.x & 3) * 32;
    int tid = threadIdx.x;

    for (int idx = tid; idx < 32*128; idx += 512) {
        int r = idx >> 7, k = idx & 127;
        LsT[k][r] = L[(r0 + r)*NN + k];
    }
    for (int idx = tid; idx < 128*32; idx += 512) {
        int k = idx >> 5, j = idx & 31;
        Rs[k][j] = R[k*NN + j0 + j];
    }
    __syncthreads();

    int r = tid >> 4;            // 0..31 (one row per thread)
    int c = (tid & 15) << 1;     // 2 cols
    float a0 = 0.0f, a1 = 0.0f;
    #pragma unroll 8
    for (int k = 0; k < 128; k++) {
        float lv = LsT[k][r];
        float2 rv = *(const float2*)&Rs[k][c];
        a0 += lv*rv.x; a1 += lv*rv.y;
    }
    int i = r0 + r;
    int base = i*NN + j0 + c;
    float acc[2] = {a0, a1};
    #pragma unroll
    for (int b = 0; b < 2; b++) {
        int j = j0 + c + b;
        float v = acc[b];
        float id = (i == j) ? 1.0f : 0.0f;
        if (dual) {
            O[base + b]   = v;
            P0m[base + b] = dI*id + dS*Sm[base + b] + dS2*S2m[base + b] + dA*v;
        } else {
            O[base + b]   = v + eI*id + eS*Sm[base + b] + eS2*S2m[base + b];
        }
    }
}

// ---------------- build row-major MA/MB/MC (512 thr, 1x2 per thread) -----
// sa diagonal computed in-kernel by mode-0 blocks (parallel, no scal kernel)
__global__ __launch_bounds__(512) void build32_kernel(const float* SB, const float* SC,
                                                      const float* YA,
                                                      const float* GA_ks1,
                                                      const float* GA_k,
                                                      const float* GA_kp1) {
    __shared__ float LsT[128][36];   // [k][r] = L[r][k]*d[k]
    __shared__ float RjT[128][36];   // [k][j] = R[j][k]
    __shared__ float ds[128];
    __shared__ float rsa[3];
    int mode = blockIdx.y;
    const float* L; const float* R;
    if (mode == 0)      { L = g_P0 + 0*MM; R = g_P0 + 0*MM; }   // A: UA_w, UA_w
    else if (mode == 1) { L = g_P0 + 1*MM; R = g_P0 + 2*MM; }   // B: UB_w, VB_w
    else                { L = g_P0 + 3*MM; R = g_P0 + 4*MM; }   // C: UC_w, VC_w
    int r0 = (blockIdx.x >> 2) * 32;
    int j0 = (blockIdx.x & 3) * 32;
    int tid = threadIdx.x;

    if (mode == 0 && tid < 32) {
        float b1=-1.0f, b2=-1.0f, c1=-1.0f, c2=-1.0f;
        #pragma unroll
        for (int u = 0; u < 4; u++) {
            int i = tid + 32*u;
            float v = fabsf(SB[i*NN + i]);
            if (v > b1) { b2 = b1; b1 = v; } else if (v > b2) b2 = v;
            float w = fabsf(SC[i*NN + i]);
            if (w > c1) { c2 = c1; c1 = w; } else if (w > c2) c2 = w;
        }
        #pragma unroll
        for (int off = 16; off; off >>= 1) {
            float ob1 = __shfl_down_sync(0xffffffffu, b1, off);
            float ob2 = __shfl_down_sync(0xffffffffu, b2, off);
            if (ob1 > b1) { b2 = fmaxf(b1, ob2); b1 = ob1; } else b2 = fmaxf(b2, ob1);
            float oc1 = __shfl_down_sync(0xffffffffu, c1, off);
            float oc2 = __shfl_down_sync(0xffffffffu, c2, off);
            if (oc1 > c1) { c2 = fmaxf(c1, oc2); c1 = oc1; } else c2 = fmaxf(c2, oc1);
        }
        if (tid == 0) {
            float sum = b1*b1*c1*c1 + b2*b2*c2*c2;
            float alpha = sqrtf(4.0f * (float)KTOP * sum);   // G = 1
            float sa0 = GA_ks1[0];
            float sa1 = -(alpha + sa0) - (fabsf(GA_k[0]) + EPSV);
            float mn = fminf(fminf(sa0, sa1), 0.0f);
            rsa[0] = sa0; rsa[1] = sa1; rsa[2] = mn;
        }
    }
    __syncthreads();
    if (tid < NN) {
        if (mode == 0)
            ds[tid] = (tid == 0) ? rsa[0]
                    : (tid == 1) ? rsa[1]
                    : rsa[2] - fabsf(GA_kp1[(tid - 2) * 127]);   // stride nsk+1
        else
            ds[tid] = (mode == 1) ? fabsf(SB[tid*NN + tid]) : fabsf(SC[tid*NN + tid]);
    }
    __syncthreads();
    for (int idx = tid; idx < 32*128; idx += 512) {
        int r = idx >> 7, k = idx & 127;
        LsT[k][r] = L[(r0 + r)*NN + k] * ds[k];
    }
    for (int idx = tid; idx < 32*128; idx += 512) {
        int j = idx >> 7, k = idx & 127;
        RjT[k][j] = R[(j0 + j)*NN + k];
    }
    __syncthreads();

    int r = tid >> 4;
    int c = (tid & 15) << 1;
    float a0 = 0.0f, a1 = 0.0f;
    #pragma unroll 8
    for (int k = 0; k < 128; k++) {
        float lv = LsT[k][r];
        float2 rv = *(const float2*)&RjT[k][c];
        a0 += lv*rv.x; a1 += lv*rv.y;
    }
    int i = r0 + r;
    float acc[2] = {a0, a1};
    #pragma unroll
    for (int b = 0; b < 2; b++) {
        int j = j0 + c + b;
        float v = acc[b];
        if (mode == 0) {   // MA = I + STEP*(0.5*UA SA UA^T + 0.5*skew(YA))
            float sk = (i < j) ? YA[i*NN + j] : ((i > j) ? -YA[j*NN + i] : 0.0f);
            g_MA[i*NN + j] = ((i == j) ? 1.0f : 0.0f)
                           + 0.5f*STEPF*v + 0.5f*STEPF*sk;
        } else if (mode == 1) {
            g_MB[i*NN + j] = STEPF * v;
        } else {
            g_MC[i*NN + j] = v;
        }
    }
}

// ---------------- recurrence: 128 blocks, 256 threads, 4 cols/block ------
// thread (r,q): row r = tid>>1, k-range [64q, 64q+64). Matrices register-
// resident as k-pair f32x2 (96 ull = 192 regs); X/T in SMEM [col][k] with
// 72-float q-pad. Biases folded into q=0 accumulator init.
#define CPAD 144   // floats per column (2*72)
#define QPAD 72    // float offset of q=1 half

__global__ __launch_bounds__(256, 1) void recur_kernel(
        const float* __restrict__ X0,
        const float* __restrict__ bx,
        const float* __restrict__ by,
        float* __restrict__ out) {
    __shared__ float sX[4*CPAD];
    __shared__ float sT[4*CPAD];
    const int tid = threadIdx.x;
    const int r = tid >> 1;
    const int q = tid & 1;
    const int b0 = blockIdx.x << 2;
    const int cw0 = 2*q, cw1 = 2*q + 1;    // columns this thread writes

    // register-resident matrix slices: 32 k-pairs per matrix
    ull rA2[32], rB2[32], rC2[32];
    {
        const ull* Ap = (const ull*)(g_MA + r*NN + 64*q);
        const ull* Bp = (const ull*)(g_MB + r*NN + 64*q);
        const ull* Cp = (const ull*)(g_MC + r*NN + 64*q);
        #pragma unroll
        for (int j = 0; j < 32; j++) { rA2[j] = Ap[j]; rB2[j] = Bp[j]; rC2[j] = Cp[j]; }
    }

    const int woff = (r >> 6)*QPAD + (r & 63);    // k=r position within a column
    float v0 = X0[(b0 + cw0)*NN + r];
    float v1 = X0[(b0 + cw1)*NN + r];
    sX[cw0*CPAD + woff] = v0;
    sX[cw1*CPAD + woff] = v1;

    float* p0 = out + ((size_t)(b0 + cw0)*TMAXS)*NN + r;
    float* p1 = out + ((size_t)(b0 + cw1)*TMAXS)*NN + r;
    *p0 = v0; *p1 = v1; p0 += NN; p1 += NN;

    const float byr = by[r];
    const float bxr = STEPF * bx[r];
    const ull byi = q ? 0ull : pk2(byr, 0.0f);   // bias fold (counted once)
    const ull bxi = q ? 0ull : pk2(bxr, 0.0f);
    __syncthreads();

    const ulonglong2* x0p = (const ulonglong2*)(sX + 0*CPAD + q*QPAD);
    const ulonglong2* x1p = (const ulonglong2*)(sX + 1*CPAD + q*QPAD);
    const ulonglong2* x2p = (const ulonglong2*)(sX + 2*CPAD + q*QPAD);
    const ulonglong2* x3p = (const ulonglong2*)(sX + 3*CPAD + q*QPAD);
    const ulonglong2* t0p = (const ulonglong2*)(sT + 0*CPAD + q*QPAD);
    const ulonglong2* t1p = (const ulonglong2*)(sT + 1*CPAD + q*QPAD);
    const ulonglong2* t2p = (const ulonglong2*)(sT + 2*CPAD + q*QPAD);
    const ulonglong2* t3p = (const ulonglong2*)(sT + 3*CPAD + q*QPAD);

    for (int t = 1; t < TMAXS; t++) {
        ull aA0=bxi, aA1=bxi, aA2=bxi, aA3=bxi;
        ull aY0=byi, aY1=byi, aY2=byi, aY3=byi;
        #pragma unroll
        for (int kk2 = 0; kk2 < 16; kk2++) {
            ulonglong2 x0 = x0p[kk2];
            ulonglong2 x1 = x1p[kk2];
            ulonglong2 x2 = x2p[kk2];
            ulonglong2 x3 = x3p[kk2];
            ull alo = rA2[2*kk2], ahi = rA2[2*kk2+1];
            ull clo = rC2[2*kk2], chi = rC2[2*kk2+1];
            fma2(aA0, alo, x0.x); fma2(aA0, ahi, x0.y);
            fma2(aA1, alo, x1.x); fma2(aA1, ahi, x1.y);
            fma2(aA2, alo, x2.x); fma2(aA2, ahi, x2.y);
            fma2(aA3, alo, x3.x); fma2(aA3, ahi, x3.y);
            fma2(aY0, clo, x0.x); fma2(aY0, chi, x0.y);
            fma2(aY1, clo, x1.x); fma2(aY1, chi, x1.y);
            fma2(aY2, clo, x2.x); fma2(aY2, chi, x2.y);
            fma2(aY3, clo, x3.x); fma2(aY3, chi, x3.y);
        }
        float lo, hi, y0, y1, y2, y3;
        unpk(lo, hi, aY0); y0 = lo + hi;
        unpk(lo, hi, aY1); y1 = lo + hi;
        unpk(lo, hi, aY2); y2 = lo + hi;
        unpk(lo, hi, aY3); y3 = lo + hi;
        ull y01 = pk2(y0, y1), y23 = pk2(y2, y3);
        ull o01 = __shfl_xor_sync(0xffffffffu, y01, 1); add2(y01, o01);
        ull o23 = __shfl_xor_sync(0xffffffffu, y23, 1); add2(y23, o23);
        float s0, s1, s2, s3;
        unpk(s0, s1, y01); unpk(s2, s3, y23);
        float tv0 = tanha(q ? s2 : s0);
        float tv1 = tanha(q ? s3 : s1);
        sT[cw0*CPAD + woff] = tv0;
        sT[cw1*CPAD + woff] = tv1;
        __syncthreads();

        #pragma unroll
        for (int kk2 = 0; kk2 < 16; kk2++) {
            ulonglong2 t0 = t0p[kk2];
            ulonglong2 t1 = t1p[kk2];
            ulonglong2 t2 = t2p[kk2];
            ulonglong2 t3 = t3p[kk2];
            ull blo = rB2[2*kk2], bhi = rB2[2*kk2+1];
            fma2(aA0, blo, t0.x); fma2(aA0, bhi, t0.y);
            fma2(aA1, blo, t1.x); fma2(aA1, bhi, t1.y);
            fma2(aA2, blo, t2.x); fma2(aA2, bhi, t2.y);
            fma2(aA3, blo, t3.x); fma2(aA3, bhi, t3.y);
        }
        float n0, n1, n2, n3;
        unpk(lo, hi, aA0); n0 = lo + hi;
        unpk(lo, hi, aA1); n1 = lo + hi;
        unpk(lo, hi, aA2); n2 = lo + hi;
        unpk(lo, hi, aA3); n3 = lo + hi;
        ull n01 = pk2(n0, n1), n23 = pk2(n2, n3);
        ull w01 = __shfl_xor_sync(0xffffffffu, n01, 1); add2(n01, w01);
        ull w23 = __shfl_xor_sync(0xffffffffu, n23, 1); add2(n23, w23);
        unpk(s0, s1, n01); unpk(s2, s3, n23);
        float xv0 = q ? s2 : s0;
        float xv1 = q ? s3 : s1;
        sX[cw0*CPAD + woff] = xv0;
        sX[cw1*CPAD + woff] = xv1;
        *p0 = xv0; *p1 = xv1; p0 += NN; p1 += NN;
        __syncthreads();
    }
}

// ---------------- host launcher ----------------
extern "C" void kernel_launch(void* const* d_in, const int* in_sizes, int n_in,
                              void* d_out, int out_size) {
    const float* X0      = (const float*)d_in[0];
    const float* GA_ks1  = (const float*)d_in[1];
    const float* GA_k    = (const float*)d_in[2];
    const float* GA_kp1  = (const float*)d_in[3];
    const float* YA      = (const float*)d_in[4];
    const float* UA      = (const float*)d_in[5];
    const float* UB      = (const float*)d_in[6];
    const float* VB      = (const float*)d_in[7];
    const float* SB      = (const float*)d_in[8];
    const float* UC      = (const float*)d_in[9];
    const float* VC      = (const float*)d_in[10];
    const float* SC      = (const float*)d_in[11];
    const float* bx      = (const float*)d_in[12];
    const float* by      = (const float*)d_in[13];
    float* out = (float*)d_out;

    // Taylor 1/m!
    const float c3 = 1.6666667e-1f, c4 = 4.1666667e-2f, c5 = 8.3333333e-3f;
    const float c6 = 1.3888889e-3f, c7 = 1.9841270e-4f, c8 = 2.4801587e-5f;
    const float c9 = 2.7557319e-6f;

    // 1) S = skew(Z)
    prep_kernel<<<dim3(5, 16), 256>>>(UA, UB, VB, UC, VC);

    // 2) expm via degree-9 Taylor, Paterson-Stockmeyer (Z = S^3), 4 GEMMs:
    //    S2 = S*S
    mm32_kernel<<<dim3(16, 5), 512>>>(0, 0, 1, 0,0,0, 0, 0,0,0,0);
    //    S3 = S2*S; dual epilogue: P0 = Q1 = c6*I + c7*S + c8*S2 + c9*S3
    mm32_kernel<<<dim3(16, 5), 512>>>(1, 0, 2, 0,0,0, 1, c6, c7, c8, c9);
    //    P1 = Q1*Z + B1
    mm32_kernel<<<dim3(16, 5), 512>>>(3, 2, 4, c3, c4, c5, 0, 0,0,0,0);
    //    P0 = P1*Z + B0   (FINAL expm in g_P0)
    mm32_kernel<<<dim3(16, 5), 512>>>(4, 2, 3, 1.0f, 1.0f, 0.5f, 0, 0,0,0,0);

    // 3) build row-major MA/MB/MC (sa diagonal computed in-kernel)
    build32_kernel<<<dim3(16, 3), 512>>>(SB, SC, YA, GA_ks1, GA_k, GA_kp1);

    // 4) sequential recurrence, batch split across 128 independent blocks
    recur_kernel<<<128, 256>>>(X0, bx, by, out);

    (void)in_sizes; (void)n_in; (void)out_size;
}